// round 1
// baseline (speedup 1.0000x reference)
#include <cuda_runtime.h>
#include <math.h>

#define C_CH 256
#define BATCH 4

// ---------------- static scratch (no allocation allowed) ----------------
__device__ float g_bufA[(size_t)BATCH * C_CH * 128 * 128];            // S1 scratch (max 128^2)
__device__ float g_bufB[(size_t)BATCH * C_CH * 256 * 256];            // ping (max 256^2)
__device__ float g_bufC[(size_t)BATCH * C_CH * 128 * 128];            // pong (max 128^2)
__device__ float g_sums[BATCH * 8 * C_CH];
__device__ float g_tot[BATCH * C_CH];
__device__ float g_cnt[BATCH * 8];
__device__ unsigned char g_lab[BATCH * 256 * 256];

// ---------------- instance norm (affine=False, eps=1e-5, population var) ----------------
__global__ void k_inorm(const float* __restrict__ in, float* __restrict__ out, int HW) {
    int bc = blockIdx.x;
    const float* p = in + (size_t)bc * HW;
    float* q = out + (size_t)bc * HW;
    float s = 0.f, s2 = 0.f;
    for (int i = threadIdx.x; i < HW; i += 256) {
        float v = p[i];
        s += v;
        s2 = fmaf(v, v, s2);
    }
#pragma unroll
    for (int o = 16; o > 0; o >>= 1) {
        s  += __shfl_xor_sync(0xffffffffu, s,  o);
        s2 += __shfl_xor_sync(0xffffffffu, s2, o);
    }
    __shared__ float sh[2][8];
    __shared__ float stat[2];
    int lane = threadIdx.x & 31, wid = threadIdx.x >> 5;
    if (lane == 0) { sh[0][wid] = s; sh[1][wid] = s2; }
    __syncthreads();
    if (threadIdx.x == 0) {
        float a = 0.f, b2 = 0.f;
#pragma unroll
        for (int w = 0; w < 8; w++) { a += sh[0][w]; b2 += sh[1][w]; }
        float invHW = 1.f / (float)HW;
        float mean = a * invHW;
        float var = b2 * invHW - mean * mean;
        stat[0] = mean;
        stat[1] = rsqrtf(var + 1e-5f);
    }
    __syncthreads();
    float mean = stat[0], inv = stat[1];
    for (int i = threadIdx.x; i < HW; i += 256)
        q[i] = (p[i] - mean) * inv;
}

// ---------------- conv 3x3, pad 1, stride 1, optional fused LeakyReLU(0.1) ----------------
// grid: (W/16, H/16, BATCH*16). block 256 = 64 quad-threads (2x2 px each) x 4 co-groups (4 co each).
template <bool RELU>
__global__ void k_conv3(const float* __restrict__ in, const float* __restrict__ w,
                        const float* __restrict__ bias, float* __restrict__ out,
                        int H, int W) {
    __shared__ float tile[18 * 19];
    __shared__ float wsm[16 * 9];
    int t = threadIdx.x;
    int cg = t >> 6;          // 0..3
    int qid = t & 63;         // 0..63
    int qy = qid >> 3, qx = qid & 7;
    int zb = blockIdx.z;
    int b = zb >> 4;
    int co0 = (zb & 15) * 16;
    int y0 = blockIdx.y * 16, x0 = blockIdx.x * 16;
    size_t in_b = (size_t)b * C_CH * H * W;

    float acc[4][4];
#pragma unroll
    for (int p = 0; p < 4; p++)
#pragma unroll
        for (int j = 0; j < 4; j++) acc[p][j] = 0.f;

    int ry = 2 * qy, rx = 2 * qx;

    for (int ci = 0; ci < C_CH; ci++) {
        __syncthreads();
        const float* ip = in + in_b + (size_t)ci * H * W;
        for (int idx = t; idx < 324; idx += 256) {
            int r = idx / 18, c = idx - r * 18;
            int gy = y0 - 1 + r, gx = x0 - 1 + c;
            float v = 0.f;
            if (gy >= 0 && gy < H && gx >= 0 && gx < W) v = ip[gy * W + gx];
            tile[r * 19 + c] = v;
        }
        if (t < 144) {
            int j = t / 9, k = t - j * 9;
            wsm[t] = w[((size_t)(co0 + j) * C_CH + ci) * 9 + k];
        }
        __syncthreads();

        float rv[4][4];
#pragma unroll
        for (int r = 0; r < 4; r++)
#pragma unroll
            for (int c = 0; c < 4; c++)
                rv[r][c] = tile[(ry + r) * 19 + rx + c];

#pragma unroll
        for (int py = 0; py < 2; py++)
#pragma unroll
            for (int px = 0; px < 2; px++) {
#pragma unroll
                for (int ky = 0; ky < 3; ky++)
#pragma unroll
                    for (int kx = 0; kx < 3; kx++) {
                        float v = rv[py + ky][px + kx];
#pragma unroll
                        for (int j = 0; j < 4; j++)
                            acc[py * 2 + px][j] =
                                fmaf(v, wsm[(cg * 4 + j) * 9 + ky * 3 + kx], acc[py * 2 + px][j]);
                    }
            }
    }

#pragma unroll
    for (int j = 0; j < 4; j++) {
        int co = co0 + cg * 4 + j;
        float bv = bias[co];
        float* op = out + ((size_t)b * C_CH + co) * H * W;
#pragma unroll
        for (int py = 0; py < 2; py++)
#pragma unroll
            for (int px = 0; px < 2; px++) {
                float v = acc[py * 2 + px][j] + bv;
                if (RELU) v = (v >= 0.f) ? v : 0.1f * v;
                op[(y0 + ry + py) * W + (x0 + rx + px)] = v;
            }
    }
}

// ---------------- ConvTranspose2d k3 s2 p1 op1 (torch weight layout Cin,Cout,3,3) ----------------
// Output quad (2i,2j)..(2i+1,2j+1) needs only input (i,j),(i,j+1),(i+1,j),(i+1,j+1).
// grid: (Win/8, Hin/8, BATCH*16). block 256 = 64 quad-threads x 4 co-groups.
template <bool ACC>
__global__ void k_convT(const float* __restrict__ in, const float* __restrict__ w,
                        const float* __restrict__ bias, float* __restrict__ out,
                        int Hin, int Win) {
    __shared__ float tile[9 * 10];
    __shared__ float wsm[16 * 9];
    int t = threadIdx.x;
    int cg = t >> 6, qid = t & 63;
    int qy = qid >> 3, qx = qid & 7;
    int zb = blockIdx.z;
    int b = zb >> 4;
    int co0 = (zb & 15) * 16;
    int i0 = blockIdx.y * 8, j0 = blockIdx.x * 8;
    int Hout = 2 * Hin, Wout = 2 * Win;

    float a_ee[4], a_eo[4], a_oe[4], a_oo[4];
#pragma unroll
    for (int j = 0; j < 4; j++) { a_ee[j] = 0.f; a_eo[j] = 0.f; a_oe[j] = 0.f; a_oo[j] = 0.f; }

    for (int ci = 0; ci < C_CH; ci++) {
        __syncthreads();
        const float* ip = in + ((size_t)b * C_CH + ci) * Hin * Win;
        if (t < 81) {
            int r = t / 9, c = t - 9 * r;
            int gy = i0 + r, gx = j0 + c;
            tile[r * 10 + c] = (gy < Hin && gx < Win) ? ip[gy * Win + gx] : 0.f;
        }
        if (t < 144) {
            int j = t / 9, k = t - 9 * j;
            wsm[t] = w[((size_t)ci * C_CH + co0 + j) * 9 + k];
        }
        __syncthreads();

        float v00 = tile[qy * 10 + qx];
        float v01 = tile[qy * 10 + qx + 1];
        float v10 = tile[(qy + 1) * 10 + qx];
        float v11 = tile[(qy + 1) * 10 + qx + 1];

#pragma unroll
        for (int j = 0; j < 4; j++) {
            const float* W9 = &wsm[(cg * 4 + j) * 9];
            a_ee[j] = fmaf(v00, W9[4], a_ee[j]);                              // (ky=1,kx=1)
            a_eo[j] = fmaf(v01, W9[3], fmaf(v00, W9[5], a_eo[j]));            // (1,0),(1,2)
            a_oe[j] = fmaf(v10, W9[1], fmaf(v00, W9[7], a_oe[j]));            // (0,1),(2,1)
            a_oo[j] = fmaf(v11, W9[0],
                      fmaf(v10, W9[2],
                      fmaf(v01, W9[6],
                      fmaf(v00, W9[8], a_oo[j]))));                           // (0,0),(0,2),(2,0),(2,2)
        }
    }

    int i = i0 + qy, jj = j0 + qx;
    int oy = 2 * i, ox = 2 * jj;
#pragma unroll
    for (int j = 0; j < 4; j++) {
        int co = co0 + cg * 4 + j;
        float bv = bias[co];
        float* op = out + ((size_t)b * C_CH + co) * Hout * Wout;
        int iee = oy * Wout + ox;
        int ieo = iee + 1;
        int ioe = iee + Wout;
        int ioo = ioe + 1;
        if (ACC) {
            op[iee] += a_ee[j] + bv;
            op[ieo] += a_eo[j] + bv;
            op[ioe] += a_oe[j] + bv;
            op[ioo] += a_oo[j] + bv;
        } else {
            op[iee] = a_ee[j] + bv;
            op[ieo] = a_eo[j] + bv;
            op[ioe] = a_oe[j] + bv;
            op[ioo] = a_oo[j] + bv;
        }
    }
}

// ---------------- 1x1 conv + tanh ----------------
// grid: (HW/256, BATCH*8). block 256, each thread 1 pixel x 32 output channels.
__global__ void k_conv1_tanh(const float* __restrict__ in, const float* __restrict__ w,
                             const float* __restrict__ bias, float* __restrict__ out, int HW) {
    __shared__ float wsm[32 * 8];
    int t = threadIdx.x;
    int b = blockIdx.y >> 3;
    int co0 = (blockIdx.y & 7) * 32;
    int p = blockIdx.x * 256 + t;
    const float* ip = in + (size_t)b * C_CH * HW + p;

    float acc[32];
#pragma unroll
    for (int j = 0; j < 32; j++) acc[j] = 0.f;

    for (int c0 = 0; c0 < C_CH; c0 += 8) {
        __syncthreads();
        if (t < 256) {
            int j = t >> 3, k = t & 7;
            wsm[t] = w[(size_t)(co0 + j) * C_CH + c0 + k];
        }
        __syncthreads();
#pragma unroll
        for (int k = 0; k < 8; k++) {
            float v = ip[(size_t)(c0 + k) * HW];
#pragma unroll
            for (int j = 0; j < 32; j++)
                acc[j] = fmaf(v, wsm[j * 8 + k], acc[j]);
        }
    }
#pragma unroll
    for (int j = 0; j < 32; j++)
        out[((size_t)b * C_CH + co0 + j) * HW + p] = tanhf(acc[j] + bias[co0 + j]);
}

// ---------------- segment label map (seg is one-hot over 8 classes; nearest map is identity) ----------------
__global__ void k_label(const float* __restrict__ seg, unsigned char* __restrict__ lab, int HW) {
    int idx = blockIdx.x * 256 + threadIdx.x;
    if (idx >= BATCH * HW) return;
    int b = idx / HW, p = idx - b * HW;
    const float* sp = seg + (size_t)b * 8 * HW + p;
    int l = 0;
#pragma unroll
    for (int s = 0; s < 8; s++)
        if (sp[(size_t)s * HW] > 0.f) l = s;
    lab[idx] = (unsigned char)l;
}

// ---------------- per-(b,c) segmented sums + global sum ----------------
__global__ void k_segreduce(const float* __restrict__ h, const unsigned char* __restrict__ lab) {
    int bc = blockIdx.x;           // B*C
    int b = bc >> 8;
    int c = bc & 255;
    const float* p = h + (size_t)bc * 65536;
    const unsigned char* lp = lab + (size_t)b * 65536;

    float acc[8];
#pragma unroll
    for (int s = 0; s < 8; s++) acc[s] = 0.f;
    float tot = 0.f;

    for (int i = threadIdx.x; i < 65536; i += 256) {
        float v = p[i];
        int l = lp[i];
        tot += v;
#pragma unroll
        for (int s = 0; s < 8; s++)
            acc[s] += (l == s) ? v : 0.f;
    }
#pragma unroll
    for (int o = 16; o > 0; o >>= 1) {
        tot += __shfl_xor_sync(0xffffffffu, tot, o);
#pragma unroll
        for (int s = 0; s < 8; s++)
            acc[s] += __shfl_xor_sync(0xffffffffu, acc[s], o);
    }
    __shared__ float sh[8][9];
    int lane = threadIdx.x & 31, wid = threadIdx.x >> 5;
    if (lane == 0) {
#pragma unroll
        for (int s = 0; s < 8; s++) sh[wid][s] = acc[s];
        sh[wid][8] = tot;
    }
    __syncthreads();
    if (threadIdx.x < 9) {
        float r = 0.f;
#pragma unroll
        for (int w2 = 0; w2 < 8; w2++) r += sh[w2][threadIdx.x];
        if (threadIdx.x < 8)
            g_sums[(b * 8 + threadIdx.x) * C_CH + c] = r;
        else
            g_tot[b * C_CH + c] = r;
    }
}

__global__ void k_counts(const unsigned char* __restrict__ lab) {
    int b = blockIdx.x;
    const unsigned char* lp = lab + (size_t)b * 65536;
    int cnt[8];
#pragma unroll
    for (int s = 0; s < 8; s++) cnt[s] = 0;
    for (int i = threadIdx.x; i < 65536; i += 256) {
        int l = lp[i];
#pragma unroll
        for (int s = 0; s < 8; s++) cnt[s] += (l == s);
    }
#pragma unroll
    for (int o = 16; o > 0; o >>= 1)
#pragma unroll
        for (int s = 0; s < 8; s++) cnt[s] += __shfl_xor_sync(0xffffffffu, cnt[s], o);
    __shared__ int sh[8][8];
    int lane = threadIdx.x & 31, wid = threadIdx.x >> 5;
    if (lane == 0)
#pragma unroll
        for (int s = 0; s < 8; s++) sh[wid][s] = cnt[s];
    __syncthreads();
    if (threadIdx.x < 8) {
        int r = 0;
#pragma unroll
        for (int w2 = 0; w2 < 8; w2++) r += sh[w2][threadIdx.x];
        g_cnt[b * 8 + threadIdx.x] = (float)r;
    }
}

// codes [B,9,C] then exist [B,8] at out[9216..9248)
__global__ void k_finalize(float* __restrict__ out) {
    int idx = blockIdx.x * 256 + threadIdx.x;
    const int NC = BATCH * 9 * C_CH;  // 9216
    if (idx < NC) {
        int b = idx / (9 * C_CH);
        int r = idx - b * 9 * C_CH;
        int s = r >> 8;
        int c = r & 255;
        float v;
        if (s < 8) {
            float cnt = g_cnt[b * 8 + s];
            v = (cnt > 0.f) ? g_sums[(b * 8 + s) * C_CH + c] / cnt : 0.f;
        } else {
            v = g_tot[b * C_CH + c] * (1.f / 65536.f);
        }
        out[idx] = v;
    } else if (idx < NC + BATCH * 8) {
        int e = idx - NC;
        out[idx] = (g_cnt[e] > 0.f) ? 1.f : 0.f;
    }
}

// ---------------- launcher ----------------
extern "C" void kernel_launch(void* const* d_in, const int* in_sizes, int n_in,
                              void* d_out, int out_size) {
    const float* x = (const float*)d_in[0];
    const float* seg = (const float*)d_in[1];

    float *A, *B, *C;
    cudaGetSymbolAddress((void**)&A, g_bufA);
    cudaGetSymbolAddress((void**)&B, g_bufB);
    cudaGetSymbolAddress((void**)&C, g_bufC);
    unsigned char* lab;
    cudaGetSymbolAddress((void**)&lab, g_lab);

    const float* X = x;
    float* OUTS[3] = {B, C, B};

    for (int blk = 0; blk < 3; blk++) {
        int H = 32 << blk;
        int HW = H * H;
        const float* wc = (const float*)d_in[2 + blk * 6 + 0];
        const float* bc = (const float*)d_in[2 + blk * 6 + 1];
        const float* wd = (const float*)d_in[2 + blk * 6 + 2];
        const float* bd = (const float*)d_in[2 + blk * 6 + 3];
        const float* ws = (const float*)d_in[2 + blk * 6 + 4];
        const float* bs = (const float*)d_in[2 + blk * 6 + 5];
        float* OUT = OUTS[blk];

        k_inorm<<<BATCH * C_CH, 256>>>(X, A, HW);
        k_conv3<true><<<dim3(H / 16, H / 16, BATCH * 16), 256>>>(A, wc, bc, OUT, H, H);
        k_inorm<<<BATCH * C_CH, 256>>>(OUT, A, HW);
        k_convT<false><<<dim3(H / 8, H / 8, BATCH * 16), 256>>>(A, wd, bd, OUT, H, H);
        k_convT<true><<<dim3(H / 8, H / 8, BATCH * 16), 256>>>(X, ws, bs, OUT, H, H);
        X = OUT;
    }

    // final 1x1 conv + tanh -> h region of d_out
    const float* w_out = (const float*)d_in[20];
    const float* b_out = (const float*)d_in[21];
    float* hout = (float*)d_out + (BATCH * 9 * C_CH + BATCH * 8);  // 9248
    k_conv1_tanh<<<dim3(65536 / 256, BATCH * 8), 256>>>(X, w_out, b_out, hout, 65536);

    // segment codes
    k_label<<<BATCH * 65536 / 256, 256>>>(seg, lab, 65536);
    k_segreduce<<<BATCH * C_CH, 256>>>(hout, lab);
    k_counts<<<BATCH, 256>>>(lab);
    k_finalize<<<(BATCH * 9 * C_CH + BATCH * 8 + 255) / 256, 256>>>((float*)d_out);
}

// round 3
// speedup vs baseline: 1.2851x; 1.2851x over previous
#include <cuda_runtime.h>
#include <math.h>

#define C_CH 256
#define BATCH 4

// ---------------- static scratch (no allocation allowed) ----------------
__device__ float g_bufA[(size_t)BATCH * C_CH * 128 * 128];   // conv3 output (max 128^2)
__device__ float g_bufB[(size_t)BATCH * C_CH * 256 * 256];   // ping (max 256^2)
__device__ float g_bufC[(size_t)BATCH * C_CH * 128 * 128];   // pong
__device__ float g_mean[BATCH * C_CH];
__device__ float g_inv[BATCH * C_CH];
__device__ float g_sums[BATCH * 8 * C_CH];
__device__ float g_tot[BATCH * C_CH];
__device__ float g_cnt[BATCH * 8];
__device__ unsigned char g_lab[BATCH * 256 * 256];

// ---------------- per-(b,c) stats for InstanceNorm (fused into conv fills) ----------------
__global__ void k_stats(const float* __restrict__ in, int HW) {
    int bc = blockIdx.x;
    const float* p = in + (size_t)bc * HW;
    float s = 0.f, s2 = 0.f;
    for (int i = threadIdx.x; i < HW; i += 256) {
        float v = p[i];
        s += v;
        s2 = fmaf(v, v, s2);
    }
#pragma unroll
    for (int o = 16; o > 0; o >>= 1) {
        s  += __shfl_xor_sync(0xffffffffu, s,  o);
        s2 += __shfl_xor_sync(0xffffffffu, s2, o);
    }
    __shared__ float sh[2][8];
    int lane = threadIdx.x & 31, wid = threadIdx.x >> 5;
    if (lane == 0) { sh[0][wid] = s; sh[1][wid] = s2; }
    __syncthreads();
    if (threadIdx.x == 0) {
        float a = 0.f, b2 = 0.f;
#pragma unroll
        for (int w = 0; w < 8; w++) { a += sh[0][w]; b2 += sh[1][w]; }
        float invHW = 1.f / (float)HW;
        float mean = a * invHW;
        float var = b2 * invHW - mean * mean;
        g_mean[bc] = mean;
        g_inv[bc] = rsqrtf(var + 1e-5f);
    }
}

// ---------------- conv 3x3 pad1 s1, input normalized on the fly, fused LeakyReLU ----------------
// block 256 = 4 co-groups x 64 qthreads; each thread: 4 rows x 2 cols x 4 co.
// block tile: 32 rows x 16 cols x 16 co. ci chunked by 4.
template <bool RELU>
__global__ void __launch_bounds__(256, 2) k_conv3(
    const float* __restrict__ in, const float* __restrict__ w,
    const float* __restrict__ bias, float* __restrict__ out, int H, int W) {
    __shared__ float tile[4][34 * 19];
    __shared__ float wsm[4][144];
    int t = threadIdx.x;
    int cg = t >> 6;
    int qid = t & 63;
    int qy = qid >> 3, qx = qid & 7;
    int b = blockIdx.z >> 4;
    int co0 = (blockIdx.z & 15) * 16;
    int y0 = blockIdx.y * 32, x0 = blockIdx.x * 16;
    int tr0 = 4 * qy, tc0 = 2 * qx;

    float acc[4][8];
#pragma unroll
    for (int j = 0; j < 4; j++)
#pragma unroll
        for (int p = 0; p < 8; p++) acc[j][p] = 0.f;

    for (int ci0 = 0; ci0 < C_CH; ci0 += 4) {
        __syncthreads();
#pragma unroll
        for (int cc = 0; cc < 4; cc++) {
            int ci = ci0 + cc;
            const float* ip = in + ((size_t)(b * C_CH + ci)) * H * W;
            float m = g_mean[b * C_CH + ci];
            float iv = g_inv[b * C_CH + ci];
            for (int idx = t; idx < 612; idx += 256) {
                int r = idx / 18, c = idx - r * 18;
                int gy = y0 - 1 + r, gx = x0 - 1 + c;
                float v = 0.f;
                if (gy >= 0 && gy < H && gx >= 0 && gx < W)
                    v = (ip[gy * W + gx] - m) * iv;
                tile[cc][r * 19 + c] = v;
            }
        }
        for (int idx = t; idx < 576; idx += 256) {
            int cc = idx / 144, rem = idx - cc * 144;
            int j = rem / 9, k = rem - 9 * j;
            wsm[cc][rem] = w[((size_t)(co0 + j) * C_CH + ci0 + cc) * 9 + k];
        }
        __syncthreads();

#pragma unroll
        for (int cc = 0; cc < 4; cc++) {
            float rv[6][4];
#pragma unroll
            for (int r = 0; r < 6; r++)
#pragma unroll
                for (int c = 0; c < 4; c++)
                    rv[r][c] = tile[cc][(tr0 + r) * 19 + tc0 + c];
#pragma unroll
            for (int j = 0; j < 4; j++) {
                float w9[9];
#pragma unroll
                for (int k = 0; k < 9; k++) w9[k] = wsm[cc][(cg * 4 + j) * 9 + k];
#pragma unroll
                for (int r = 0; r < 4; r++)
#pragma unroll
                    for (int c = 0; c < 2; c++) {
#pragma unroll
                        for (int ky = 0; ky < 3; ky++)
#pragma unroll
                            for (int kx = 0; kx < 3; kx++)
                                acc[j][r * 2 + c] = fmaf(rv[r + ky][c + kx], w9[ky * 3 + kx], acc[j][r * 2 + c]);
                    }
            }
        }
    }

#pragma unroll
    for (int j = 0; j < 4; j++) {
        int co = co0 + cg * 4 + j;
        float bv = bias[co];
        float* op = out + ((size_t)(b * C_CH + co)) * H * W;
#pragma unroll
        for (int r = 0; r < 4; r++) {
            float v0 = acc[j][r * 2 + 0] + bv;
            float v1 = acc[j][r * 2 + 1] + bv;
            if (RELU) {
                v0 = (v0 >= 0.f) ? v0 : 0.1f * v0;
                v1 = (v1 >= 0.f) ? v1 : 0.1f * v1;
            }
            *reinterpret_cast<float2*>(op + (y0 + tr0 + r) * W + x0 + tc0) = make_float2(v0, v1);
        }
    }
}

// ---------------- fused dual ConvTranspose2d (k3 s2 p1 op1) ----------------
// out = convT(norm(src1), w1) + b1 + convT(src2, w2) + b2
// block 256 = 4 co-groups x 64 qthreads; each thread: 2x2 input quads x 4 co -> 4x4 outputs.
// block input region 16x16 -> 32x32 output. ci chunked by 4.
__global__ void __launch_bounds__(256, 2) k_convT_dual(
    const float* __restrict__ src1, const float* __restrict__ w1,
    const float* __restrict__ src2, const float* __restrict__ w2,
    const float* __restrict__ b1, const float* __restrict__ b2,
    float* __restrict__ out, int Hin, int Win) {
    __shared__ float tile[4][17 * 18];
    __shared__ float wsm[4][144];
    int t = threadIdx.x;
    int cg = t >> 6;
    int qid = t & 63;
    int qy = qid >> 3, qx = qid & 7;
    int b = blockIdx.z >> 4;
    int co0 = (blockIdx.z & 15) * 16;
    int i0 = blockIdx.y * 16, j0 = blockIdx.x * 16;
    int ti0 = 2 * qy, tj0 = 2 * qx;

    float4 acc[4][4];
#pragma unroll
    for (int j = 0; j < 4; j++)
#pragma unroll
        for (int q = 0; q < 4; q++) acc[j][q] = make_float4(0.f, 0.f, 0.f, 0.f);

    for (int s = 0; s < 2; s++) {
        const float* src = s ? src2 : src1;
        const float* ww = s ? w2 : w1;
        for (int ci0 = 0; ci0 < C_CH; ci0 += 4) {
            __syncthreads();
#pragma unroll
            for (int cc = 0; cc < 4; cc++) {
                int ci = ci0 + cc;
                const float* ip = src + ((size_t)(b * C_CH + ci)) * Hin * Win;
                float m = s ? 0.f : g_mean[b * C_CH + ci];
                float iv = s ? 1.f : g_inv[b * C_CH + ci];
                for (int idx = t; idx < 289; idx += 256) {
                    int r = idx / 17, c = idx - r * 17;
                    int gy = i0 + r, gx = j0 + c;
                    float v = 0.f;
                    if (gy < Hin && gx < Win) v = (ip[gy * Win + gx] - m) * iv;
                    tile[cc][r * 18 + c] = v;
                }
            }
            for (int idx = t; idx < 576; idx += 256) {
                int cc = idx / 144, rem = idx - cc * 144;
                int j = rem / 9, k = rem - 9 * j;
                wsm[cc][rem] = ww[((size_t)(ci0 + cc) * C_CH + co0 + j) * 9 + k];
            }
            __syncthreads();

#pragma unroll
            for (int cc = 0; cc < 4; cc++) {
                float v[3][3];
#pragma unroll
                for (int r = 0; r < 3; r++)
#pragma unroll
                    for (int c = 0; c < 3; c++)
                        v[r][c] = tile[cc][(ti0 + r) * 18 + tj0 + c];
#pragma unroll
                for (int j = 0; j < 4; j++) {
                    float w9[9];
#pragma unroll
                    for (int k = 0; k < 9; k++) w9[k] = wsm[cc][(cg * 4 + j) * 9 + k];
#pragma unroll
                    for (int iy = 0; iy < 2; iy++)
#pragma unroll
                        for (int ix = 0; ix < 2; ix++) {
                            int q = iy * 2 + ix;
                            float v00 = v[iy][ix], v01 = v[iy][ix + 1];
                            float v10 = v[iy + 1][ix], v11 = v[iy + 1][ix + 1];
                            acc[j][q].x = fmaf(v00, w9[4], acc[j][q].x);
                            acc[j][q].y = fmaf(v00, w9[5], fmaf(v01, w9[3], acc[j][q].y));
                            acc[j][q].z = fmaf(v00, w9[7], fmaf(v10, w9[1], acc[j][q].z));
                            acc[j][q].w = fmaf(v00, w9[8], fmaf(v01, w9[6],
                                          fmaf(v10, w9[2], fmaf(v11, w9[0], acc[j][q].w))));
                        }
                }
            }
        }
    }

    int Wout = 2 * Win;
    int gi = i0 + ti0, gj = j0 + tj0;
#pragma unroll
    for (int j = 0; j < 4; j++) {
        int co = co0 + cg * 4 + j;
        float bv = b1[co] + b2[co];
        float* op = out + ((size_t)(b * C_CH + co)) * (size_t)Hin * Win * 4;
#pragma unroll
        for (int iy = 0; iy < 2; iy++) {
            int ye = 2 * (gi + iy);
            float4 re = make_float4(acc[j][iy * 2 + 0].x + bv, acc[j][iy * 2 + 0].y + bv,
                                    acc[j][iy * 2 + 1].x + bv, acc[j][iy * 2 + 1].y + bv);
            float4 ro = make_float4(acc[j][iy * 2 + 0].z + bv, acc[j][iy * 2 + 0].w + bv,
                                    acc[j][iy * 2 + 1].z + bv, acc[j][iy * 2 + 1].w + bv);
            *reinterpret_cast<float4*>(op + (size_t)ye * Wout + 2 * gj) = re;
            *reinterpret_cast<float4*>(op + (size_t)(ye + 1) * Wout + 2 * gj) = ro;
        }
    }
}

// ---------------- 1x1 conv + tanh : each thread 4 px x 16 co ----------------
__global__ void __launch_bounds__(256, 2) k_conv1_tanh(
    const float* __restrict__ in, const float* __restrict__ w,
    const float* __restrict__ bias, float* __restrict__ out, int HW) {
    __shared__ float wsm[128];
    int t = threadIdx.x;
    int b = blockIdx.y >> 4;
    int co0 = (blockIdx.y & 15) * 16;
    int p0 = blockIdx.x * 1024;
    const float* ip = in + (size_t)b * C_CH * HW + p0 + t;

    float acc[16][4];
#pragma unroll
    for (int j = 0; j < 16; j++)
#pragma unroll
        for (int i = 0; i < 4; i++) acc[j][i] = 0.f;

    for (int c0 = 0; c0 < C_CH; c0 += 8) {
        __syncthreads();
        if (t < 128) {
            int j = t >> 3, k = t & 7;
            wsm[t] = w[(size_t)(co0 + j) * C_CH + c0 + k];
        }
        __syncthreads();
#pragma unroll
        for (int k = 0; k < 8; k++) {
            const float* p = ip + (size_t)(c0 + k) * HW;
            float v0 = p[0], v1 = p[256], v2 = p[512], v3 = p[768];
#pragma unroll
            for (int j = 0; j < 16; j++) {
                float wv = wsm[j * 8 + k];
                acc[j][0] = fmaf(v0, wv, acc[j][0]);
                acc[j][1] = fmaf(v1, wv, acc[j][1]);
                acc[j][2] = fmaf(v2, wv, acc[j][2]);
                acc[j][3] = fmaf(v3, wv, acc[j][3]);
            }
        }
    }
#pragma unroll
    for (int j = 0; j < 16; j++) {
        int co = co0 + j;
        float bv = bias[co];
        float* op = out + ((size_t)(b * C_CH + co)) * HW + p0 + t;
        op[0] = tanhf(acc[j][0] + bv);
        op[256] = tanhf(acc[j][1] + bv);
        op[512] = tanhf(acc[j][2] + bv);
        op[768] = tanhf(acc[j][3] + bv);
    }
}

// ---------------- segment label map ----------------
__global__ void k_label(const float* __restrict__ seg, unsigned char* __restrict__ lab, int HW) {
    int idx = blockIdx.x * 256 + threadIdx.x;
    if (idx >= BATCH * HW) return;
    int b = idx / HW, p = idx - b * HW;
    const float* sp = seg + (size_t)b * 8 * HW + p;
    int l = 0;
#pragma unroll
    for (int s = 0; s < 8; s++)
        if (sp[(size_t)s * HW] > 0.f) l = s;
    lab[idx] = (unsigned char)l;
}

// ---------------- per-(b,c) segmented sums + global sum ----------------
__global__ void k_segreduce(const float* __restrict__ h, const unsigned char* __restrict__ lab) {
    int bc = blockIdx.x;
    int b = bc >> 8;
    int c = bc & 255;
    const float* p = h + (size_t)bc * 65536;
    const unsigned char* lp = lab + (size_t)b * 65536;

    float acc[8];
#pragma unroll
    for (int s = 0; s < 8; s++) acc[s] = 0.f;
    float tot = 0.f;

    for (int i = threadIdx.x; i < 65536; i += 256) {
        float v = p[i];
        int l = lp[i];
        tot += v;
#pragma unroll
        for (int s = 0; s < 8; s++)
            acc[s] += (l == s) ? v : 0.f;
    }
#pragma unroll
    for (int o = 16; o > 0; o >>= 1) {
        tot += __shfl_xor_sync(0xffffffffu, tot, o);
#pragma unroll
        for (int s = 0; s < 8; s++)
            acc[s] += __shfl_xor_sync(0xffffffffu, acc[s], o);
    }
    __shared__ float sh[8][9];
    int lane = threadIdx.x & 31, wid = threadIdx.x >> 5;
    if (lane == 0) {
#pragma unroll
        for (int s = 0; s < 8; s++) sh[wid][s] = acc[s];
        sh[wid][8] = tot;
    }
    __syncthreads();
    if (threadIdx.x < 9) {
        float r = 0.f;
#pragma unroll
        for (int w2 = 0; w2 < 8; w2++) r += sh[w2][threadIdx.x];
        if (threadIdx.x < 8)
            g_sums[(b * 8 + threadIdx.x) * C_CH + c] = r;
        else
            g_tot[b * C_CH + c] = r;
    }
}

__global__ void k_counts(const unsigned char* __restrict__ lab) {
    int b = blockIdx.x;
    const unsigned char* lp = lab + (size_t)b * 65536;
    int cnt[8];
#pragma unroll
    for (int s = 0; s < 8; s++) cnt[s] = 0;
    for (int i = threadIdx.x; i < 65536; i += 256) {
        int l = lp[i];
#pragma unroll
        for (int s = 0; s < 8; s++) cnt[s] += (l == s);
    }
#pragma unroll
    for (int o = 16; o > 0; o >>= 1)
#pragma unroll
        for (int s = 0; s < 8; s++) cnt[s] += __shfl_xor_sync(0xffffffffu, cnt[s], o);
    __shared__ int sh[8][8];
    int lane = threadIdx.x & 31, wid = threadIdx.x >> 5;
    if (lane == 0)
#pragma unroll
        for (int s = 0; s < 8; s++) sh[wid][s] = cnt[s];
    __syncthreads();
    if (threadIdx.x < 8) {
        int r = 0;
#pragma unroll
        for (int w2 = 0; w2 < 8; w2++) r += sh[w2][threadIdx.x];
        g_cnt[b * 8 + threadIdx.x] = (float)r;
    }
}

// codes [B,9,C] then exist [B,8]
__global__ void k_finalize(float* __restrict__ out) {
    int idx = blockIdx.x * 256 + threadIdx.x;
    const int NC = BATCH * 9 * C_CH;  // 9216
    if (idx < NC) {
        int b = idx / (9 * C_CH);
        int r = idx - b * 9 * C_CH;
        int s = r >> 8;
        int c = r & 255;
        float v;
        if (s < 8) {
            float cnt = g_cnt[b * 8 + s];
            v = (cnt > 0.f) ? g_sums[(b * 8 + s) * C_CH + c] / cnt : 0.f;
        } else {
            v = g_tot[b * C_CH + c] * (1.f / 65536.f);
        }
        out[idx] = v;
    } else if (idx < NC + BATCH * 8) {
        int e = idx - NC;
        out[idx] = (g_cnt[e] > 0.f) ? 1.f : 0.f;
    }
}

// ---------------- launcher ----------------
extern "C" void kernel_launch(void* const* d_in, const int* in_sizes, int n_in,
                              void* d_out, int out_size) {
    const float* x = (const float*)d_in[0];
    const float* seg = (const float*)d_in[1];

    float *A, *B, *C;
    cudaGetSymbolAddress((void**)&A, g_bufA);
    cudaGetSymbolAddress((void**)&B, g_bufB);
    cudaGetSymbolAddress((void**)&C, g_bufC);
    unsigned char* lab;
    cudaGetSymbolAddress((void**)&lab, g_lab);

    const float* X = x;
    float* OUTS[3] = {B, C, B};

    for (int blk = 0; blk < 3; blk++) {
        int H = 32 << blk;
        int HW = H * H;
        const float* wc = (const float*)d_in[2 + blk * 6 + 0];
        const float* bc = (const float*)d_in[2 + blk * 6 + 1];
        const float* wd = (const float*)d_in[2 + blk * 6 + 2];
        const float* bd = (const float*)d_in[2 + blk * 6 + 3];
        const float* ws = (const float*)d_in[2 + blk * 6 + 4];
        const float* bs = (const float*)d_in[2 + blk * 6 + 5];
        float* OUT = OUTS[blk];

        k_stats<<<BATCH * C_CH, 256>>>(X, HW);
        k_conv3<true><<<dim3(H / 16, H / 32, BATCH * 16), 256>>>(X, wc, bc, A, H, H);
        k_stats<<<BATCH * C_CH, 256>>>(A, HW);
        k_convT_dual<<<dim3(H / 16, H / 16, BATCH * 16), 256>>>(A, wd, X, ws, bd, bs, OUT, H, H);
        X = OUT;
    }

    // final 1x1 conv + tanh -> h region of d_out
    const float* w_out = (const float*)d_in[20];
    const float* b_out = (const float*)d_in[21];
    float* hout = (float*)d_out + (BATCH * 9 * C_CH + BATCH * 8);  // 9248
    k_conv1_tanh<<<dim3(64, BATCH * 16), 256>>>(X, w_out, b_out, hout, 65536);

    // segment codes
    k_label<<<BATCH * 65536 / 256, 256>>>(seg, lab, 65536);
    k_segreduce<<<BATCH * C_CH, 256>>>(hout, lab);
    k_counts<<<BATCH, 256>>>(lab);
    k_finalize<<<(BATCH * 9 * C_CH + BATCH * 8 + 255) / 256, 256>>>((float*)d_out);
}

// round 4
// speedup vs baseline: 2.1508x; 1.6737x over previous
#include <cuda_runtime.h>
#include <cuda_pipeline.h>
#include <math.h>

#define C_CH 256
#define BATCH 4
#define BC (BATCH * C_CH)

// ---------------- static scratch (no allocation allowed) ----------------
// Padded layout per (b,c) plane: pitch P = W+4, rows H+2.
// Data at rows 1..H, cols 2..W+1. Zero halo everywhere else.
__device__ float g_Xn[(size_t)BC * 130 * 132];   // padded norm(X), max H=128
__device__ float g_An[(size_t)BC * 130 * 132];   // padded norm(A)
__device__ float g_A [(size_t)BC * 128 * 128];   // conv3 output, unpadded
__device__ float g_Xp[(size_t)BC * 34 * 36];     // padded raw x (stage1 shortcut src)
__device__ float g_P1[(size_t)BC * 66 * 68];     // stage1 convT out (padded, H=64)
__device__ float g_P2[(size_t)BC * 130 * 132];   // stage2 convT out (padded, H=128)
__device__ float g_P3[(size_t)BC * 258 * 260];   // stage3 convT out (padded, H=256)
__device__ float g_mean[BC];
__device__ float g_inv[BC];
__device__ float g_sums[BATCH * 8 * C_CH];
__device__ float g_tot[BATCH * C_CH];
__device__ float g_cnt[BATCH * 8];
__device__ unsigned char g_lab[BATCH * 256 * 256];

// ---------------- per-(b,c) stats for InstanceNorm ----------------
__global__ void k_stats(const float* __restrict__ in, int lw, int pitch, int off, int plane) {
    int bc = blockIdx.x;
    int W = 1 << lw;
    int HW = W * W;
    const float* p = in + (size_t)bc * plane + off;
    float s = 0.f, s2 = 0.f;
    for (int i = threadIdx.x; i < HW; i += 256) {
        int r = i >> lw, c = i & (W - 1);
        float v = p[r * pitch + c];
        s += v;
        s2 = fmaf(v, v, s2);
    }
#pragma unroll
    for (int o = 16; o > 0; o >>= 1) {
        s  += __shfl_xor_sync(0xffffffffu, s,  o);
        s2 += __shfl_xor_sync(0xffffffffu, s2, o);
    }
    __shared__ float sh[2][8];
    int lane = threadIdx.x & 31, wid = threadIdx.x >> 5;
    if (lane == 0) { sh[0][wid] = s; sh[1][wid] = s2; }
    __syncthreads();
    if (threadIdx.x == 0) {
        float a = 0.f, b2 = 0.f;
#pragma unroll
        for (int w = 0; w < 8; w++) { a += sh[0][w]; b2 += sh[1][w]; }
        float invHW = 1.f / (float)HW;
        float mean = a * invHW;
        float var = b2 * invHW - mean * mean;
        g_mean[bc] = mean;
        g_inv[bc] = rsqrtf(var + 1e-5f);
    }
}

// ---------------- normalize (or identity pad-copy) into padded layout ----------------
// grid (BC, H+2), block 256. Writes full padded rows including zero halo.
__global__ void k_normalize(const float* __restrict__ src, float* __restrict__ dst,
                            int H, int W, int spitch, int soff, int splane, int ident) {
    int bc = blockIdx.x, rp = blockIdx.y;
    int P = W + 4;
    int dplane = (H + 2) * P;
    float m = 0.f, iv = 1.f;
    if (!ident) { m = g_mean[bc]; iv = g_inv[bc]; }
    float* d = dst + (size_t)bc * dplane + (size_t)rp * P;
    bool rowOK = (rp >= 1 && rp <= H);
    const float* s = src + (size_t)bc * splane + soff + (size_t)(rp - 1) * spitch;
    for (int c2 = threadIdx.x; c2 < P; c2 += 256) {
        float v = 0.f;
        if (rowOK && c2 >= 2 && c2 < W + 2) v = (s[c2 - 2] - m) * iv;
        d[c2] = v;
    }
}

// ---------------- zero the halo of a convT output buffer (interior written by convT) ----------------
__global__ void k_border(float* __restrict__ buf, int H2, int P2) {
    int bc = blockIdx.x;
    int plane = (H2 + 2) * P2;
    float* p = buf + (size_t)bc * plane;
    for (int i = threadIdx.x; i < P2; i += 256) {
        p[i] = 0.f;
        p[(size_t)(H2 + 1) * P2 + i] = 0.f;
    }
    for (int i = threadIdx.x; i < H2; i += 256) {
        float* r = p + (size_t)(i + 1) * P2;
        r[0] = 0.f; r[1] = 0.f; r[P2 - 2] = 0.f; r[P2 - 1] = 0.f;
    }
}

// ---------------- conv 3x3 pad1 s1 on padded normalized input, fused LeakyReLU ----------------
// NCO output channels per block. block 256 = 4 co-groups x 64 qthreads.
// Each thread: 4 rows x 2 cols x (NCO/4) co. Block tile 32 rows x 16 cols.
// cp.async double-buffered over ci chunks of 4.
template <int NCO>
__global__ void __launch_bounds__(256, 2) k_conv3(
    const float* __restrict__ in, const float* __restrict__ w,
    const float* __restrict__ bias, float* __restrict__ out, int H) {
    constexpr int J = NCO / 4;
    __shared__ __align__(16) float tile[2][4][34 * 19];
    __shared__ __align__(16) float wsm[2][4][NCO * 9];
    int t = threadIdx.x;
    int cg = t >> 6;
    int qid = t & 63;
    int qy = qid >> 3, qx = qid & 7;
    const int zdiv = 256 / NCO;
    int b = blockIdx.z / zdiv;
    int co0 = (blockIdx.z % zdiv) * NCO;
    int y0 = blockIdx.y * 32, x0 = blockIdx.x * 16;
    int P = H + 4;
    int plane = (H + 2) * P;
    int tr0 = 4 * qy, tc0 = 2 * qx;
    const size_t inb = (size_t)b * C_CH * plane;

    float acc[J][8];
#pragma unroll
    for (int j = 0; j < J; j++)
#pragma unroll
        for (int p = 0; p < 8; p++) acc[j][p] = 0.f;

    int fcc = t >> 6, fi = t & 63;

#define C3_FILL(CI0, BUF)                                                                 \
    {                                                                                     \
        const float* sp = in + inb + (size_t)((CI0) + fcc) * plane + (size_t)y0 * P + x0 + 1; \
        _Pragma("unroll")                                                                 \
        for (int it = 0; it < 10; it++) {                                                 \
            int e = fi + 64 * it;                                                         \
            if (e < 612) {                                                                \
                int r = e / 18, c = e - r * 18;                                           \
                __pipeline_memcpy_async(&tile[BUF][fcc][r * 19 + c], sp + r * P + c, 4);  \
            }                                                                             \
        }                                                                                 \
        for (int idx = t; idx < 4 * NCO * 9; idx += 256) {                                \
            int cc2 = idx / (NCO * 9), rem = idx - cc2 * (NCO * 9);                       \
            int j = rem / 9, k = rem - 9 * j;                                             \
            __pipeline_memcpy_async(&wsm[BUF][cc2][rem],                                  \
                w + ((size_t)(co0 + j) * C_CH + (CI0) + cc2) * 9 + k, 4);                 \
        }                                                                                 \
    }

    C3_FILL(0, 0);
    __pipeline_commit();
    for (int m = 0; m < 64; m++) {
        if (m + 1 < 64) { C3_FILL((m + 1) * 4, (m + 1) & 1); }
        __pipeline_commit();
        __pipeline_wait_prior(1);
        __syncthreads();
        int cur = m & 1;
#pragma unroll
        for (int cc = 0; cc < 4; cc++) {
            float rv[6][4];
#pragma unroll
            for (int r = 0; r < 6; r++)
#pragma unroll
                for (int c = 0; c < 4; c++)
                    rv[r][c] = tile[cur][cc][(tr0 + r) * 19 + tc0 + c];
#pragma unroll
            for (int j = 0; j < J; j++) {
                float w9[9];
#pragma unroll
                for (int k = 0; k < 9; k++) w9[k] = wsm[cur][cc][(cg * J + j) * 9 + k];
#pragma unroll
                for (int r = 0; r < 4; r++)
#pragma unroll
                    for (int c = 0; c < 2; c++) {
#pragma unroll
                        for (int ky = 0; ky < 3; ky++)
#pragma unroll
                            for (int kx = 0; kx < 3; kx++)
                                acc[j][r * 2 + c] = fmaf(rv[r + ky][c + kx], w9[ky * 3 + kx], acc[j][r * 2 + c]);
                    }
            }
        }
        __syncthreads();
    }
#undef C3_FILL

#pragma unroll
    for (int j = 0; j < J; j++) {
        int co = co0 + cg * J + j;
        float bv = bias[co];
        float* op = out + ((size_t)(b * C_CH + co)) * H * H;
#pragma unroll
        for (int r = 0; r < 4; r++) {
            float v0 = acc[j][r * 2 + 0] + bv;
            float v1 = acc[j][r * 2 + 1] + bv;
            v0 = (v0 >= 0.f) ? v0 : 0.1f * v0;
            v1 = (v1 >= 0.f) ? v1 : 0.1f * v1;
            *reinterpret_cast<float2*>(op + (y0 + tr0 + r) * H + x0 + tc0) = make_float2(v0, v1);
        }
    }
}

// ---------------- fused dual ConvTranspose2d (k3 s2 p1 op1), padded in/out ----------------
// out(padded) = convT(s1=norm(A), w1) + b1 + convT(s2=X, w2) + b2
// block 256 = 4 co-groups x 64 qthreads; each thread 2x2 input quads x (NCO/4) co.
// Uniform pipeline over 128 chunks (2 sources x 64 ci-chunks of 4).
template <int NCO>
__global__ void __launch_bounds__(256, 2) k_convT(
    const float* __restrict__ s1, const float* __restrict__ w1,
    const float* __restrict__ s2, const float* __restrict__ w2,
    const float* __restrict__ b1, const float* __restrict__ b2,
    float* __restrict__ out, int Hin) {
    constexpr int J = NCO / 4;
    constexpr int W4 = NCO * 9 / 4;
    __shared__ __align__(16) float tile[2][4][17 * 18];
    __shared__ __align__(16) float wsm[2][4][NCO * 9];
    int t = threadIdx.x;
    int cg = t >> 6;
    int qid = t & 63;
    int qy = qid >> 3, qx = qid & 7;
    const int zdiv = 256 / NCO;
    int b = blockIdx.z / zdiv;
    int co0 = (blockIdx.z % zdiv) * NCO;
    int i0 = blockIdx.y * 16, j0 = blockIdx.x * 16;
    int Pin = Hin + 4;
    int plin = (Hin + 2) * Pin;
    int Pout = 2 * Hin + 4;
    size_t plout = (size_t)(2 * Hin + 2) * Pout;
    int ti0 = 2 * qy, tj0 = 2 * qx;

    float4 acc[J][4];
#pragma unroll
    for (int j = 0; j < J; j++)
#pragma unroll
        for (int q = 0; q < 4; q++) acc[j][q] = make_float4(0.f, 0.f, 0.f, 0.f);

    int fcc = t >> 6, fi = t & 63;

#define CT_FILL(M, BUF)                                                                    \
    {                                                                                      \
        int s_ = (M) >> 6;                                                                 \
        int ci0_ = ((M) & 63) * 4;                                                         \
        const float* src_ = s_ ? s2 : s1;                                                  \
        const float* ww_ = s_ ? w2 : w1;                                                   \
        const float* sp = src_ + ((size_t)(b * C_CH + ci0_ + fcc)) * plin                  \
                          + (size_t)(i0 + 1) * Pin + (j0 + 2);                             \
        _Pragma("unroll")                                                                  \
        for (int it = 0; it < 5; it++) {                                                   \
            int e = fi + 64 * it;                                                          \
            if (e < 289) {                                                                 \
                int r = e / 17, c = e - r * 17;                                            \
                __pipeline_memcpy_async(&tile[BUF][fcc][r * 18 + c], sp + r * Pin + c, 4); \
            }                                                                              \
        }                                                                                  \
        if (t < 4 * W4) {                                                                  \
            int cc2 = t / W4, v = t - cc2 * W4;                                            \
            __pipeline_memcpy_async(&wsm[BUF][cc2][v * 4],                                 \
                ww_ + ((size_t)(ci0_ + cc2) * C_CH + co0) * 9 + v * 4, 16);                \
        }                                                                                  \
    }

    CT_FILL(0, 0);
    __pipeline_commit();
    for (int m = 0; m < 128; m++) {
        if (m + 1 < 128) { CT_FILL(m + 1, (m + 1) & 1); }
        __pipeline_commit();
        __pipeline_wait_prior(1);
        __syncthreads();
        int cur = m & 1;
#pragma unroll
        for (int cc = 0; cc < 4; cc++) {
            float v[3][3];
#pragma unroll
            for (int r = 0; r < 3; r++)
#pragma unroll
                for (int c = 0; c < 3; c++)
                    v[r][c] = tile[cur][cc][(ti0 + r) * 18 + tj0 + c];
#pragma unroll
            for (int j = 0; j < J; j++) {
                float w9[9];
#pragma unroll
                for (int k = 0; k < 9; k++) w9[k] = wsm[cur][cc][(cg * J + j) * 9 + k];
#pragma unroll
                for (int iy = 0; iy < 2; iy++)
#pragma unroll
                    for (int ix = 0; ix < 2; ix++) {
                        int q = iy * 2 + ix;
                        float v00 = v[iy][ix], v01 = v[iy][ix + 1];
                        float v10 = v[iy + 1][ix], v11 = v[iy + 1][ix + 1];
                        acc[j][q].x = fmaf(v00, w9[4], acc[j][q].x);
                        acc[j][q].y = fmaf(v00, w9[5], fmaf(v01, w9[3], acc[j][q].y));
                        acc[j][q].z = fmaf(v00, w9[7], fmaf(v10, w9[1], acc[j][q].z));
                        acc[j][q].w = fmaf(v00, w9[8], fmaf(v01, w9[6],
                                      fmaf(v10, w9[2], fmaf(v11, w9[0], acc[j][q].w))));
                    }
            }
        }
        __syncthreads();
    }
#undef CT_FILL

    int gi = i0 + ti0, gj = j0 + tj0;
#pragma unroll
    for (int j = 0; j < J; j++) {
        int co = co0 + cg * J + j;
        float bv = b1[co] + b2[co];
        float* op = out + (size_t)(b * C_CH + co) * plout;
#pragma unroll
        for (int iy = 0; iy < 2; iy++) {
            size_t rowE = (size_t)(2 * (gi + iy) + 1) * Pout + 2 * gj + 2;
            float4 a0 = acc[j][iy * 2 + 0];
            float4 a1 = acc[j][iy * 2 + 1];
            *reinterpret_cast<float2*>(op + rowE)            = make_float2(a0.x + bv, a0.y + bv);
            *reinterpret_cast<float2*>(op + rowE + 2)        = make_float2(a1.x + bv, a1.y + bv);
            *reinterpret_cast<float2*>(op + rowE + Pout)     = make_float2(a0.z + bv, a0.w + bv);
            *reinterpret_cast<float2*>(op + rowE + Pout + 2) = make_float2(a1.z + bv, a1.w + bv);
        }
    }
}

// ---------------- 1x1 conv + tanh, padded input (g_P3) -> unpadded h in d_out ----------------
__global__ void __launch_bounds__(256, 2) k_conv1_tanh(
    const float* __restrict__ in, const float* __restrict__ w,
    const float* __restrict__ bias, float* __restrict__ out) {
    const int PLANE = 258 * 260;
    __shared__ float wsm[128];
    int t = threadIdx.x;
    int b = blockIdx.y >> 4;
    int co0 = (blockIdx.y & 15) * 16;
    int p0 = blockIdx.x * 1024;
    const float* base = in + (size_t)b * C_CH * PLANE;

    int off[4];
#pragma unroll
    for (int i = 0; i < 4; i++) {
        int p = p0 + t + 256 * i;
        int r = p >> 8, c = p & 255;
        off[i] = (r + 1) * 260 + c + 2;
    }

    float acc[16][4];
#pragma unroll
    for (int j = 0; j < 16; j++)
#pragma unroll
        for (int i = 0; i < 4; i++) acc[j][i] = 0.f;

    for (int c0 = 0; c0 < C_CH; c0 += 8) {
        __syncthreads();
        if (t < 128) {
            int j = t >> 3, k = t & 7;
            wsm[t] = w[(size_t)(co0 + j) * C_CH + c0 + k];
        }
        __syncthreads();
#pragma unroll
        for (int k = 0; k < 8; k++) {
            const float* p = base + (size_t)(c0 + k) * PLANE;
            float v0 = p[off[0]], v1 = p[off[1]], v2 = p[off[2]], v3 = p[off[3]];
#pragma unroll
            for (int j = 0; j < 16; j++) {
                float wv = wsm[j * 8 + k];
                acc[j][0] = fmaf(v0, wv, acc[j][0]);
                acc[j][1] = fmaf(v1, wv, acc[j][1]);
                acc[j][2] = fmaf(v2, wv, acc[j][2]);
                acc[j][3] = fmaf(v3, wv, acc[j][3]);
            }
        }
    }
#pragma unroll
    for (int j = 0; j < 16; j++) {
        int co = co0 + j;
        float bv = bias[co];
        float* op = out + ((size_t)(b * C_CH + co)) * 65536 + p0 + t;
        op[0]   = tanhf(acc[j][0] + bv);
        op[256] = tanhf(acc[j][1] + bv);
        op[512] = tanhf(acc[j][2] + bv);
        op[768] = tanhf(acc[j][3] + bv);
    }
}

// ---------------- segment label map ----------------
__global__ void k_label(const float* __restrict__ seg, unsigned char* __restrict__ lab, int HW) {
    int idx = blockIdx.x * 256 + threadIdx.x;
    if (idx >= BATCH * HW) return;
    int b = idx / HW, p = idx - b * HW;
    const float* sp = seg + (size_t)b * 8 * HW + p;
    int l = 0;
#pragma unroll
    for (int s = 0; s < 8; s++)
        if (sp[(size_t)s * HW] > 0.f) l = s;
    lab[idx] = (unsigned char)l;
}

// ---------------- per-(b,c) segmented sums + global sum ----------------
__global__ void k_segreduce(const float* __restrict__ h, const unsigned char* __restrict__ lab) {
    int bc = blockIdx.x;
    int b = bc >> 8;
    int c = bc & 255;
    const float* p = h + (size_t)bc * 65536;
    const unsigned char* lp = lab + (size_t)b * 65536;

    float acc[8];
#pragma unroll
    for (int s = 0; s < 8; s++) acc[s] = 0.f;
    float tot = 0.f;

    for (int i = threadIdx.x; i < 65536; i += 256) {
        float v = p[i];
        int l = lp[i];
        tot += v;
#pragma unroll
        for (int s = 0; s < 8; s++)
            acc[s] += (l == s) ? v : 0.f;
    }
#pragma unroll
    for (int o = 16; o > 0; o >>= 1) {
        tot += __shfl_xor_sync(0xffffffffu, tot, o);
#pragma unroll
        for (int s = 0; s < 8; s++)
            acc[s] += __shfl_xor_sync(0xffffffffu, acc[s], o);
    }
    __shared__ float sh[8][9];
    int lane = threadIdx.x & 31, wid = threadIdx.x >> 5;
    if (lane == 0) {
#pragma unroll
        for (int s = 0; s < 8; s++) sh[wid][s] = acc[s];
        sh[wid][8] = tot;
    }
    __syncthreads();
    if (threadIdx.x < 9) {
        float r = 0.f;
#pragma unroll
        for (int w2 = 0; w2 < 8; w2++) r += sh[w2][threadIdx.x];
        if (threadIdx.x < 8)
            g_sums[(b * 8 + threadIdx.x) * C_CH + c] = r;
        else
            g_tot[b * C_CH + c] = r;
    }
}

__global__ void k_counts(const unsigned char* __restrict__ lab) {
    int b = blockIdx.x;
    const unsigned char* lp = lab + (size_t)b * 65536;
    int cnt[8];
#pragma unroll
    for (int s = 0; s < 8; s++) cnt[s] = 0;
    for (int i = threadIdx.x; i < 65536; i += 256) {
        int l = lp[i];
#pragma unroll
        for (int s = 0; s < 8; s++) cnt[s] += (l == s);
    }
#pragma unroll
    for (int o = 16; o > 0; o >>= 1)
#pragma unroll
        for (int s = 0; s < 8; s++) cnt[s] += __shfl_xor_sync(0xffffffffu, cnt[s], o);
    __shared__ int sh[8][8];
    int lane = threadIdx.x & 31, wid = threadIdx.x >> 5;
    if (lane == 0)
#pragma unroll
        for (int s = 0; s < 8; s++) sh[wid][s] = cnt[s];
    __syncthreads();
    if (threadIdx.x < 8) {
        int r = 0;
#pragma unroll
        for (int w2 = 0; w2 < 8; w2++) r += sh[w2][threadIdx.x];
        g_cnt[b * 8 + threadIdx.x] = (float)r;
    }
}

// codes [B,9,C] then exist [B,8]
__global__ void k_finalize(float* __restrict__ out) {
    int idx = blockIdx.x * 256 + threadIdx.x;
    const int NC = BATCH * 9 * C_CH;  // 9216
    if (idx < NC) {
        int b = idx / (9 * C_CH);
        int r = idx - b * 9 * C_CH;
        int s = r >> 8;
        int c = r & 255;
        float v;
        if (s < 8) {
            float cnt = g_cnt[b * 8 + s];
            v = (cnt > 0.f) ? g_sums[(b * 8 + s) * C_CH + c] / cnt : 0.f;
        } else {
            v = g_tot[b * C_CH + c] * (1.f / 65536.f);
        }
        out[idx] = v;
    } else if (idx < NC + BATCH * 8) {
        int e = idx - NC;
        out[idx] = (g_cnt[e] > 0.f) ? 1.f : 0.f;
    }
}

// ---------------- launcher ----------------
extern "C" void kernel_launch(void* const* d_in, const int* in_sizes, int n_in,
                              void* d_out, int out_size) {
    const float* x = (const float*)d_in[0];
    const float* seg = (const float*)d_in[1];

    float *Xn, *An, *A, *Xp, *P1, *P2, *P3;
    cudaGetSymbolAddress((void**)&Xn, g_Xn);
    cudaGetSymbolAddress((void**)&An, g_An);
    cudaGetSymbolAddress((void**)&A, g_A);
    cudaGetSymbolAddress((void**)&Xp, g_Xp);
    cudaGetSymbolAddress((void**)&P1, g_P1);
    cudaGetSymbolAddress((void**)&P2, g_P2);
    cudaGetSymbolAddress((void**)&P3, g_P3);
    unsigned char* lab;
    cudaGetSymbolAddress((void**)&lab, g_lab);

    // per-stage X source descriptors
    const float* Xsrc[3] = {x, P1, P2};
    float* OUT[3] = {P1, P2, P3};
    const int Hs[3] = {32, 64, 128};
    const int lws[3] = {5, 6, 7};
    // X layout params (stage1 raw, stages 2/3 padded)
    const int Xpitch[3] = {32, 68, 132};
    const int Xoff[3]   = {0, 70, 134};
    const int Xplane[3] = {1024, 66 * 68, 130 * 132};

    for (int blk = 0; blk < 3; blk++) {
        int H = Hs[blk];
        const float* wc = (const float*)d_in[2 + blk * 6 + 0];
        const float* bc = (const float*)d_in[2 + blk * 6 + 1];
        const float* wd = (const float*)d_in[2 + blk * 6 + 2];
        const float* bd = (const float*)d_in[2 + blk * 6 + 3];
        const float* ws = (const float*)d_in[2 + blk * 6 + 4];
        const float* bs = (const float*)d_in[2 + blk * 6 + 5];
        const float* X = Xsrc[blk];

        // norm(X) -> Xn (padded)
        k_stats<<<BC, 256>>>(X, lws[blk], Xpitch[blk], Xoff[blk], Xplane[blk]);
        k_normalize<<<dim3(BC, H + 2), 256>>>(X, Xn, H, H, Xpitch[blk], Xoff[blk], Xplane[blk], 0);
        // stage1: pad raw x for the shortcut convT source
        const float* S2 = (blk == 0) ? Xp : X;
        if (blk == 0)
            k_normalize<<<dim3(BC, 34), 256>>>(x, Xp, 32, 32, 32, 0, 1024, 1);

        // conv3 + LeakyReLU -> A (unpadded)
        if (blk == 0)
            k_conv3<8><<<dim3(H / 16, H / 32, BATCH * 32), 256>>>(Xn, wc, bc, A, H);
        else
            k_conv3<16><<<dim3(H / 16, H / 32, BATCH * 16), 256>>>(Xn, wc, bc, A, H);

        // norm(A) -> An (padded)
        k_stats<<<BC, 256>>>(A, lws[blk], H, 0, H * H);
        k_normalize<<<dim3(BC, H + 2), 256>>>(A, An, H, H, H, 0, H * H, 0);

        // zero halo of OUT, then fused dual convT writes interior
        k_border<<<BC, 256>>>(OUT[blk], 2 * H, 2 * H + 4);
        if (blk == 0)
            k_convT<8><<<dim3(H / 16, H / 16, BATCH * 32), 256>>>(An, wd, S2, ws, bd, bs, OUT[blk], H);
        else
            k_convT<16><<<dim3(H / 16, H / 16, BATCH * 16), 256>>>(An, wd, S2, ws, bd, bs, OUT[blk], H);
    }

    // final 1x1 conv + tanh -> h region of d_out
    const float* w_out = (const float*)d_in[20];
    const float* b_out = (const float*)d_in[21];
    float* hout = (float*)d_out + (BATCH * 9 * C_CH + BATCH * 8);  // 9248
    k_conv1_tanh<<<dim3(64, BATCH * 16), 256>>>(P3, w_out, b_out, hout);

    // segment codes
    k_label<<<BATCH * 65536 / 256, 256>>>(seg, lab, 65536);
    k_segreduce<<<BATCH * C_CH, 256>>>(hout, lab);
    k_counts<<<BATCH, 256>>>(lab);
    k_finalize<<<(BATCH * 9 * C_CH + BATCH * 8 + 255) / 256, 256>>>((float*)d_out);
}